// round 12
// baseline (speedup 1.0000x reference)
#include <cuda_runtime.h>
#include <math.h>

// Problem constants (fixed shapes)
#define NPTS   16384
#define MPTS   4096          // NPTS / STRIDE(4)
#define KNN    16
#define DIN    64
#define DF     67            // 3 + DIN
#define DOUT   128
#define NCHUNK 8
#define CHSZ   (NPTS / NCHUNK)   // 2048
#define FPS_T  1024
#define PPT    (NPTS / FPS_T)    // 16
#define NBINS  4096              // 16x16x16 Morton cells

#define F_INF  __int_as_float(0x7f800000)

// ---------------- scratch (static device allocations; no cudaMalloc) -------
__device__ float g_cand_d[MPTS * NCHUNK * KNN];
__device__ int   g_cand_i[MPTS * NCHUNK * KNN];
__device__ float g_feat[MPTS * DF];
__device__ float g_h[MPTS * DOUT];
__device__ float g_scale[DOUT];
__device__ float g_shift[DOUT];
__device__ float g_sx[NPTS];
__device__ float g_sy[NPTS];
__device__ float g_sz[NPTS];
__device__ int   g_sidx[NPTS];     // sorted position -> original index
__device__ int   g_code[NPTS];

// ---------------------------------------------------------------------------
// 0) Preprocess: bbox -> Morton cell id (16^3) -> counting sort of coords
//    (keeping original indices). Single block. The sort only changes
//    scheduling; all FPS comparisons use ORIGINAL indices so results match
//    the reference bit-for-bit, including ties.
// ---------------------------------------------------------------------------
__device__ __forceinline__ unsigned mort4(unsigned x)
{
    return (x & 1u) | ((x & 2u) << 2) | ((x & 4u) << 4) | ((x & 8u) << 6);
}

__global__ __launch_bounds__(1024, 1)
void prep_kernel(const float* __restrict__ p)
{
    __shared__ int   sh_hist[NBINS];
    __shared__ float sh_r[32][6];
    __shared__ float sh_bb[6];
    __shared__ int   sh_wt[32];

    const int tid  = threadIdx.x;
    const int lane = tid & 31;
    const int wid  = tid >> 5;

    // ---- bbox reduce ----
    float mnx = F_INF, mny = F_INF, mnz = F_INF;
    float mxx = -F_INF, mxy = -F_INF, mxz = -F_INF;
    for (int j = 0; j < PPT; j++) {
        const int i = tid + (j << 10);
        float px = p[3 * i + 0], py = p[3 * i + 1], pz = p[3 * i + 2];
        mnx = fminf(mnx, px); mxx = fmaxf(mxx, px);
        mny = fminf(mny, py); mxy = fmaxf(mxy, py);
        mnz = fminf(mnz, pz); mxz = fmaxf(mxz, pz);
    }
#pragma unroll
    for (int off = 16; off > 0; off >>= 1) {
        mnx = fminf(mnx, __shfl_xor_sync(0xffffffffu, mnx, off));
        mny = fminf(mny, __shfl_xor_sync(0xffffffffu, mny, off));
        mnz = fminf(mnz, __shfl_xor_sync(0xffffffffu, mnz, off));
        mxx = fmaxf(mxx, __shfl_xor_sync(0xffffffffu, mxx, off));
        mxy = fmaxf(mxy, __shfl_xor_sync(0xffffffffu, mxy, off));
        mxz = fmaxf(mxz, __shfl_xor_sync(0xffffffffu, mxz, off));
    }
    if (lane == 0) {
        sh_r[wid][0] = mnx; sh_r[wid][1] = mny; sh_r[wid][2] = mnz;
        sh_r[wid][3] = mxx; sh_r[wid][4] = mxy; sh_r[wid][5] = mxz;
    }
    __syncthreads();
    if (wid == 0) {
        mnx = sh_r[lane][0]; mny = sh_r[lane][1]; mnz = sh_r[lane][2];
        mxx = sh_r[lane][3]; mxy = sh_r[lane][4]; mxz = sh_r[lane][5];
#pragma unroll
        for (int off = 16; off > 0; off >>= 1) {
            mnx = fminf(mnx, __shfl_xor_sync(0xffffffffu, mnx, off));
            mny = fminf(mny, __shfl_xor_sync(0xffffffffu, mny, off));
            mnz = fminf(mnz, __shfl_xor_sync(0xffffffffu, mnz, off));
            mxx = fmaxf(mxx, __shfl_xor_sync(0xffffffffu, mxx, off));
            mxy = fmaxf(mxy, __shfl_xor_sync(0xffffffffu, mxy, off));
            mxz = fmaxf(mxz, __shfl_xor_sync(0xffffffffu, mxz, off));
        }
        if (lane == 0) {
            sh_bb[0] = mnx; sh_bb[1] = mny; sh_bb[2] = mnz;
            sh_bb[3] = mxx; sh_bb[4] = mxy; sh_bb[5] = mxz;
        }
    }
    // zero hist
    for (int i = tid; i < NBINS; i += 1024) sh_hist[i] = 0;
    __syncthreads();

    const float bx0 = sh_bb[0], by0 = sh_bb[1], bz0 = sh_bb[2];
    const float ivx = 16.0f / fmaxf(sh_bb[3] - bx0, 1e-20f);
    const float ivy = 16.0f / fmaxf(sh_bb[4] - by0, 1e-20f);
    const float ivz = 16.0f / fmaxf(sh_bb[5] - bz0, 1e-20f);

    // ---- codes + histogram ----
    for (int j = 0; j < PPT; j++) {
        const int i = tid + (j << 10);
        float px = p[3 * i + 0], py = p[3 * i + 1], pz = p[3 * i + 2];
        int cx = min(15, max(0, (int)((px - bx0) * ivx)));
        int cy = min(15, max(0, (int)((py - by0) * ivy)));
        int cz = min(15, max(0, (int)((pz - bz0) * ivz)));
        int code = (int)(mort4((unsigned)cx) | (mort4((unsigned)cy) << 1)
                         | (mort4((unsigned)cz) << 2));
        g_code[i] = code;
        atomicAdd(&sh_hist[code], 1);
    }
    __syncthreads();

    // ---- exclusive scan of 4096 bins (4 per thread) ----
    int b0 = sh_hist[4 * tid + 0];
    int b1 = sh_hist[4 * tid + 1];
    int b2 = sh_hist[4 * tid + 2];
    int b3 = sh_hist[4 * tid + 3];
    int tsum = b0 + b1 + b2 + b3;
    int v = tsum;
#pragma unroll
    for (int off = 1; off < 32; off <<= 1) {
        int n = __shfl_up_sync(0xffffffffu, v, off);
        if (lane >= off) v += n;
    }
    const int excl = v - tsum;
    if (lane == 31) sh_wt[wid] = v;
    __syncthreads();
    if (wid == 0) {
        int wv = sh_wt[lane];
        int sv = wv;
#pragma unroll
        for (int off = 1; off < 32; off <<= 1) {
            int n = __shfl_up_sync(0xffffffffu, sv, off);
            if (lane >= off) sv += n;
        }
        sh_wt[lane] = sv - wv;  // exclusive warp offsets
    }
    __syncthreads();
    const int toff = sh_wt[wid] + excl;
    sh_hist[4 * tid + 0] = toff;
    sh_hist[4 * tid + 1] = toff + b0;
    sh_hist[4 * tid + 2] = toff + b0 + b1;
    sh_hist[4 * tid + 3] = toff + b0 + b1 + b2;
    __syncthreads();

    // ---- scatter sorted coords + original indices ----
    for (int j = 0; j < PPT; j++) {
        const int i = tid + (j << 10);
        const int code = g_code[i];
        const int pos = atomicAdd(&sh_hist[code], 1);
        g_sx[pos] = p[3 * i + 0];
        g_sy[pos] = p[3 * i + 1];
        g_sz[pos] = p[3 * i + 2];
        g_sidx[pos] = i;
    }
}

// ---------------------------------------------------------------------------
// 1) FPS, hierarchical exact pruning (warp bbox -> chunk bbox), SINGLE
//    barrier per iteration:
//      active warps scan + level-1 butterfly -> lane0 STS red[parity][wid]
//      __syncthreads
//      EVERY warp redundantly reduces the 32 warp results (level-2
//      butterfly) and loads the winner's coords itself (broadcast LDS).
//    Double-buffered red[] keeps iterations race-free with one barrier.
//    d[]-evolution and comparator are bit-identical to brute force:
//    exact non-FMA distance math, packed key (orig<<14)|sorted gives
//    jnp.argmax first-occurrence tie-breaks.
// ---------------------------------------------------------------------------
__global__ __launch_bounds__(FPS_T, 1)
void fps_kernel(const float* __restrict__ p, float* __restrict__ np_out)
{
    extern __shared__ float sm[];
    float* sxT = sm;                 // [16][1024]
    float* syT = sm + NPTS;
    float* szT = sm + 2 * NPTS;
    __shared__ float red_v[2][32];
    __shared__ int   red_os[2][32];

    const int tid  = threadIdx.x;
    const int lane = tid & 31;
    const int wid  = tid >> 5;

    // load sorted coords, transposed: sorted index i -> [(i&15)][i>>4]
    for (int j = 0; j < PPT; j++) {
        const int i = tid + (j << 10);
        const int col = ((i & 15) << 10) | (i >> 4);
        sxT[col] = g_sx[i];
        syT[col] = g_sy[i];
        szT[col] = g_sz[i];
    }

    // packed keys of owned points: (orig<<14)|sorted
    int osk[PPT];
#pragma unroll
    for (int k = 0; k < PPT; k++)
        osk[k] = (g_sidx[(tid << 4) | k] << 14) | ((tid << 4) | k);

    float lx = p[0], ly = p[1], lz = p[2];
    if (tid == 0) { np_out[0] = lx; np_out[1] = ly; np_out[2] = lz; }
    __syncthreads();

    // chunk bbox (registers)
    float bxl = F_INF, byl = F_INF, bzl = F_INF;
    float bxh = -F_INF, byh = -F_INF, bzh = -F_INF;
#pragma unroll
    for (int k = 0; k < PPT; k++) {
        const int col = (k << 10) | tid;
        float x = sxT[col], y = syT[col], z = szT[col];
        bxl = fminf(bxl, x); bxh = fmaxf(bxh, x);
        byl = fminf(byl, y); byh = fmaxf(byh, y);
        bzl = fminf(bzl, z); bzh = fmaxf(bzh, z);
    }

    // warp bbox = union of the 32 lane bboxes (butterfly; all lanes converge)
    float wxl = bxl, wyl = byl, wzl = bzl;
    float wxh = bxh, wyh = byh, wzh = bzh;
#pragma unroll
    for (int off = 16; off > 0; off >>= 1) {
        wxl = fminf(wxl, __shfl_xor_sync(0xffffffffu, wxl, off));
        wyl = fminf(wyl, __shfl_xor_sync(0xffffffffu, wyl, off));
        wzl = fminf(wzl, __shfl_xor_sync(0xffffffffu, wzl, off));
        wxh = fmaxf(wxh, __shfl_xor_sync(0xffffffffu, wxh, off));
        wyh = fmaxf(wyh, __shfl_xor_sync(0xffffffffu, wyh, off));
        wzh = fmaxf(wzh, __shfl_xor_sync(0xffffffffu, wzh, off));
    }

    float d[PPT];
#pragma unroll
    for (int k = 0; k < PPT; k++) d[k] = F_INF;
    float my_v  = F_INF;           // per-chunk cached max min-dist
    int   my_os = 0x7fffffff;
    float wv  = F_INF;             // per-warp cached reduce result
    int   wos = 0x7fffffff;

    for (int it = 1; it < MPTS; it++) {
        const int ph = it & 1;

        // warp-level lower bound (uniform across lanes)
        float ewx = fmaxf(fmaxf(wxl - lx, lx - wxh), 0.0f);
        float ewy = fmaxf(fmaxf(wyl - ly, ly - wyh), 0.0f);
        float ewz = fmaxf(fmaxf(wzl - lz, lz - wzh), 0.0f);
        float lbw = ewx * ewx + ewy * ewy + ewz * ewz;

        if (lbw < wv * 1.00002f) {
            // chunk-level bound
            float ex = fmaxf(fmaxf(bxl - lx, lx - bxh), 0.0f);
            float ey = fmaxf(fmaxf(byl - ly, ly - byh), 0.0f);
            float ez = fmaxf(fmaxf(bzl - lz, lz - bzh), 0.0f);
            float lb = ex * ex + ey * ey + ez * ez;

            if (lb < my_v * 1.00002f) {
                float bv = -1.0f;
                int   bos = 0x7fffffff;
#pragma unroll
                for (int k = 0; k < PPT; k++) {
                    const int col = (k << 10) | tid;
                    float dx = __fsub_rn(sxT[col], lx);
                    float dy = __fsub_rn(syT[col], ly);
                    float dz = __fsub_rn(szT[col], lz);
                    float s  = __fadd_rn(__fadd_rn(__fmul_rn(dx, dx), __fmul_rn(dy, dy)),
                                         __fmul_rn(dz, dz));
                    float dn = fminf(d[k], s);
                    d[k] = dn;
                    if (dn > bv || (dn == bv && osk[k] < bos)) { bv = dn; bos = osk[k]; }
                }
                my_v = bv; my_os = bos;
            }
            // level-1 butterfly (all lanes converge)
            float rv = my_v; int ros = my_os;
#pragma unroll
            for (int off = 16; off > 0; off >>= 1) {
                float ov = __shfl_xor_sync(0xffffffffu, rv, off);
                int   oo = __shfl_xor_sync(0xffffffffu, ros, off);
                if (ov > rv || (ov == rv && oo < ros)) { rv = ov; ros = oo; }
            }
            wv = rv; wos = ros;
        }
        if (lane == 0) { red_v[ph][wid] = wv; red_os[ph][wid] = wos; }
        __syncthreads();

        // level-2: every warp reduces the 32 per-warp results redundantly
        float rv = red_v[ph][lane];
        int   ros = red_os[ph][lane];
#pragma unroll
        for (int off = 16; off > 0; off >>= 1) {
            float ov = __shfl_xor_sync(0xffffffffu, rv, off);
            int   oo = __shfl_xor_sync(0xffffffffu, ros, off);
            if (ov > rv || (ov == rv && oo < ros)) { rv = ov; ros = oo; }
        }
        const int rs  = ros & 0x3FFF;
        const int col = ((rs & 15) << 10) | (rs >> 4);
        lx = sxT[col]; ly = syT[col]; lz = szT[col];   // broadcast LDS
        if (tid == 0) {
            np_out[3 * it + 0] = lx;
            np_out[3 * it + 1] = ly;
            np_out[3 * it + 2] = lz;
        }
    }
}

// ---------------------------------------------------------------------------
// 2) kNN phase A: one thread per (query, chunk). Chunk coords staged in smem;
//    register-resident sorted top-16 with bubble insert.
// ---------------------------------------------------------------------------
__global__ __launch_bounds__(256)
void knn_kernel(const float* __restrict__ p, const float* __restrict__ np)
{
    __shared__ float sx[CHSZ], sy[CHSZ], sz[CHSZ];
    const int c = blockIdx.y;
    const int q = blockIdx.x * blockDim.x + threadIdx.x;

    for (int i = threadIdx.x; i < CHSZ; i += blockDim.x) {
        const int g = c * CHSZ + i;
        sx[i] = p[3 * g + 0];
        sy[i] = p[3 * g + 1];
        sz[i] = p[3 * g + 2];
    }
    __syncthreads();

    const float qx = np[3 * q + 0];
    const float qy = np[3 * q + 1];
    const float qz = np[3 * q + 2];

    float dk[KNN];
    int   ik[KNN];
#pragma unroll
    for (int t = 0; t < KNN; t++) { dk[t] = F_INF; ik[t] = 0; }

    for (int j = 0; j < CHSZ; j++) {
        float dx = qx - sx[j];
        float dy = qy - sy[j];
        float dz = qz - sz[j];
        float d2 = dx * dx + dy * dy + dz * dz;
        if (d2 < dk[KNN - 1]) {
            float cd = d2;
            int   ci = c * CHSZ + j;
#pragma unroll
            for (int t = 0; t < KNN; t++) {
                if (cd < dk[t]) {
                    float td = dk[t]; int ti = ik[t];
                    dk[t] = cd; ik[t] = ci;
                    cd = td; ci = ti;
                }
            }
        }
    }
    const int base = (q * NCHUNK + c) * KNN;
#pragma unroll
    for (int t = 0; t < KNN; t++) {
        g_cand_d[base + t] = dk[t];
        g_cand_i[base + t] = ik[t];
    }
}

// ---------------------------------------------------------------------------
// 3) Merge 8 sorted candidate lists -> top-16 set, gather, normalize,
//    max-pool to 67 dims. One warp per query.
// ---------------------------------------------------------------------------
__global__ __launch_bounds__(128)
void feat_kernel(const float* __restrict__ p, const float* __restrict__ x,
                 const float* __restrict__ np)
{
    const int w    = threadIdx.x >> 5;
    const int lane = threadIdx.x & 31;
    const int q    = blockIdx.x * 4 + w;

    __shared__ int s_nn[4][KNN];

    if (lane == 0) {
        int hpos[NCHUNK];
#pragma unroll
        for (int c = 0; c < NCHUNK; c++) hpos[c] = 0;
        for (int t = 0; t < KNN; t++) {
            float best = F_INF;
            int   bc   = 0;
#pragma unroll
            for (int c = 0; c < NCHUNK; c++) {
                float v = g_cand_d[(q * NCHUNK + c) * KNN + hpos[c]];
                if (v < best) { best = v; bc = c; }
            }
            s_nn[w][t] = g_cand_i[(q * NCHUNK + bc) * KNN + hpos[bc]];
            hpos[bc]++;
        }
    }
    __syncwarp();

    const float qx = np[3 * q + 0];
    const float qy = np[3 * q + 1];
    const float qz = np[3 * q + 2];

    float nr = -1.0f;
    if (lane < KNN) {
        int j = s_nn[w][lane];
        float rx = p[3 * j + 0] - qx;
        float ry = p[3 * j + 1] - qy;
        float rz = p[3 * j + 2] - qz;
        nr = sqrtf(rx * rx + ry * ry + rz * rz);
    }
#pragma unroll
    for (int off = 16; off > 0; off >>= 1)
        nr = fmaxf(nr, __shfl_xor_sync(0xffffffffu, nr, off));
    const float den = nr + 1e-8f;

    if (lane < 3) {
        const float qc = (lane == 0) ? qx : (lane == 1) ? qy : qz;
        float mv = -F_INF;
#pragma unroll
        for (int k = 0; k < KNN; k++) {
            int j = s_nn[w][k];
            mv = fmaxf(mv, p[3 * j + lane] - qc);
        }
        g_feat[q * DF + lane] = mv / den;
    }

    for (int xd = lane; xd < DIN; xd += 32) {
        float mv = -F_INF;
#pragma unroll
        for (int k = 0; k < KNN; k++) {
            int j = s_nn[w][k];
            mv = fmaxf(mv, x[j * DIN + xd]);
        }
        g_feat[q * DF + 3 + xd] = mv;
    }
}

// ---------------------------------------------------------------------------
// 4) h = feat @ W + b   (tiny GEMM: 4096x67x128)
// ---------------------------------------------------------------------------
__global__ __launch_bounds__(1024)
void mlp_kernel(const float* __restrict__ W, const float* __restrict__ b)
{
    __shared__ float sW[DF * DOUT];
    __shared__ float sF[8][DF];
    const int tid = threadIdx.x;
    for (int i = tid; i < DF * DOUT; i += 1024) sW[i] = W[i];
    const int qb = blockIdx.x * 8;
    for (int i = tid; i < 8 * DF; i += 1024) {
        int qq = i / DF, f = i - qq * DF;
        sF[qq][f] = g_feat[(qb + qq) * DF + f];
    }
    __syncthreads();
    const int od = tid & 127;
    const int qi = tid >> 7;
    float acc = b[od];
#pragma unroll
    for (int f = 0; f < DF; f++) acc += sF[qi][f] * sW[f * DOUT + od];
    g_h[(qb + qi) * DOUT + od] = acc;
}

// ---------------------------------------------------------------------------
// 5) BatchNorm training stats per output column (double accumulation)
// ---------------------------------------------------------------------------
__global__ __launch_bounds__(256)
void bn_stats_kernel(const float* __restrict__ gamma, const float* __restrict__ beta)
{
    const int col = blockIdx.x;
    const int tid = threadIdx.x;
    double s = 0.0, s2 = 0.0;
    for (int q = tid; q < MPTS; q += 256) {
        float v = g_h[q * DOUT + col];
        s  += (double)v;
        s2 += (double)v * (double)v;
    }
    __shared__ double sh_s[256], sh_s2[256];
    sh_s[tid] = s; sh_s2[tid] = s2;
    __syncthreads();
    for (int off = 128; off > 0; off >>= 1) {
        if (tid < off) { sh_s[tid] += sh_s[tid + off]; sh_s2[tid] += sh_s2[tid + off]; }
        __syncthreads();
    }
    if (tid == 0) {
        double mean = sh_s[0] / (double)MPTS;
        double var  = sh_s2[0] / (double)MPTS - mean * mean;
        float inv   = (float)(1.0 / sqrt(var + 1e-5));
        float sc    = gamma[col] * inv;
        g_scale[col] = sc;
        g_shift[col] = beta[col] - (float)mean * sc;
    }
}

// ---------------------------------------------------------------------------
// 6) normalize + ReLU -> output; write n_o tail
// ---------------------------------------------------------------------------
__global__ __launch_bounds__(1024)
void finalize_kernel(float* __restrict__ out, int tail)
{
    const int idx = blockIdx.x * 1024 + threadIdx.x;
    if (idx < MPTS * DOUT) {
        const int od = idx & 127;
        float v = g_h[idx] * g_scale[od] + g_shift[od];
        out[3 * MPTS + idx] = v > 0.0f ? v : 0.0f;
    }
    if (idx == 0) {
        for (int t = 0; t < tail; t++)
            out[3 * MPTS + MPTS * DOUT + t] = (float)MPTS;
    }
}

// ---------------------------------------------------------------------------
extern "C" void kernel_launch(void* const* d_in, const int* in_sizes, int n_in,
                              void* d_out, int out_size)
{
    const float* p     = (const float*)d_in[0];
    const float* x     = (const float*)d_in[1];
    // d_in[2] = offsets o (unused, single cloud)
    const float* W     = (const float*)d_in[3];
    const float* b     = (const float*)d_in[4];
    const float* gamma = (const float*)d_in[5];
    const float* beta  = (const float*)d_in[6];
    float* out = (float*)d_out;

    cudaFuncSetAttribute(fps_kernel, cudaFuncAttributeMaxDynamicSharedMemorySize,
                         3 * NPTS * (int)sizeof(float));

    prep_kernel<<<1, 1024>>>(p);

    fps_kernel<<<1, FPS_T, 3 * NPTS * sizeof(float)>>>(p, out);

    dim3 gA(MPTS / 256, NCHUNK);
    knn_kernel<<<gA, 256>>>(p, out);

    feat_kernel<<<MPTS / 4, 128>>>(p, x, out);

    mlp_kernel<<<MPTS / 8, 1024>>>(W, b);

    bn_stats_kernel<<<DOUT, 256>>>(gamma, beta);

    int tail = out_size - (3 * MPTS + MPTS * DOUT);
    if (tail < 0) tail = 0;
    finalize_kernel<<<(MPTS * DOUT + 1023) / 1024, 1024>>>(out, tail);
}

// round 17
// speedup vs baseline: 1.2492x; 1.2492x over previous
#include <cuda_runtime.h>
#include <math.h>

// Problem constants (fixed shapes)
#define NPTS   16384
#define MPTS   4096          // NPTS / STRIDE(4)
#define KNN    16
#define DIN    64
#define DF     67            // 3 + DIN
#define DOUT   128
#define NCHUNK 8
#define CHSZ   (NPTS / NCHUNK)   // 2048
#define NBINS  4096              // 16x16x16 Morton cells

#define FPS_T  512
#define PPT    (NPTS / FPS_T)    // 32 points per thread
#define NWARP  (FPS_T / 32)      // 16

#define F_INF  __int_as_float(0x7f800000)

// ---------------- scratch (static device allocations; no cudaMalloc) -------
__device__ float g_cand_d[MPTS * NCHUNK * KNN];
__device__ int   g_cand_i[MPTS * NCHUNK * KNN];
__device__ float g_feat[MPTS * DF];
__device__ float g_h[MPTS * DOUT];
__device__ float g_scale[DOUT];
__device__ float g_shift[DOUT];
__device__ float g_sx[NPTS];
__device__ float g_sy[NPTS];
__device__ float g_sz[NPTS];
__device__ int   g_sidx[NPTS];     // sorted position -> original index
__device__ int   g_code[NPTS];

// ---------------------------------------------------------------------------
// 0) Preprocess: bbox -> Morton cell id (16^3) -> counting sort of coords
//    (keeping original indices). Single block (1024 threads). The sort only
//    changes scheduling; all FPS comparisons use ORIGINAL indices so results
//    match the reference bit-for-bit, including ties.
// ---------------------------------------------------------------------------
__device__ __forceinline__ unsigned mort4(unsigned x)
{
    return (x & 1u) | ((x & 2u) << 2) | ((x & 4u) << 4) | ((x & 8u) << 6);
}

__global__ __launch_bounds__(1024, 1)
void prep_kernel(const float* __restrict__ p)
{
    __shared__ int   sh_hist[NBINS];
    __shared__ float sh_r[32][6];
    __shared__ float sh_bb[6];
    __shared__ int   sh_wt[32];

    const int tid  = threadIdx.x;
    const int lane = tid & 31;
    const int wid  = tid >> 5;

    // ---- bbox reduce ----
    float mnx = F_INF, mny = F_INF, mnz = F_INF;
    float mxx = -F_INF, mxy = -F_INF, mxz = -F_INF;
    for (int j = 0; j < 16; j++) {
        const int i = tid + (j << 10);
        float px = p[3 * i + 0], py = p[3 * i + 1], pz = p[3 * i + 2];
        mnx = fminf(mnx, px); mxx = fmaxf(mxx, px);
        mny = fminf(mny, py); mxy = fmaxf(mxy, py);
        mnz = fminf(mnz, pz); mxz = fmaxf(mxz, pz);
    }
#pragma unroll
    for (int off = 16; off > 0; off >>= 1) {
        mnx = fminf(mnx, __shfl_xor_sync(0xffffffffu, mnx, off));
        mny = fminf(mny, __shfl_xor_sync(0xffffffffu, mny, off));
        mnz = fminf(mnz, __shfl_xor_sync(0xffffffffu, mnz, off));
        mxx = fmaxf(mxx, __shfl_xor_sync(0xffffffffu, mxx, off));
        mxy = fmaxf(mxy, __shfl_xor_sync(0xffffffffu, mxy, off));
        mxz = fmaxf(mxz, __shfl_xor_sync(0xffffffffu, mxz, off));
    }
    if (lane == 0) {
        sh_r[wid][0] = mnx; sh_r[wid][1] = mny; sh_r[wid][2] = mnz;
        sh_r[wid][3] = mxx; sh_r[wid][4] = mxy; sh_r[wid][5] = mxz;
    }
    __syncthreads();
    if (wid == 0) {
        mnx = sh_r[lane][0]; mny = sh_r[lane][1]; mnz = sh_r[lane][2];
        mxx = sh_r[lane][3]; mxy = sh_r[lane][4]; mxz = sh_r[lane][5];
#pragma unroll
        for (int off = 16; off > 0; off >>= 1) {
            mnx = fminf(mnx, __shfl_xor_sync(0xffffffffu, mnx, off));
            mny = fminf(mny, __shfl_xor_sync(0xffffffffu, mny, off));
            mnz = fminf(mnz, __shfl_xor_sync(0xffffffffu, mnz, off));
            mxx = fmaxf(mxx, __shfl_xor_sync(0xffffffffu, mxx, off));
            mxy = fmaxf(mxy, __shfl_xor_sync(0xffffffffu, mxy, off));
            mxz = fmaxf(mxz, __shfl_xor_sync(0xffffffffu, mxz, off));
        }
        if (lane == 0) {
            sh_bb[0] = mnx; sh_bb[1] = mny; sh_bb[2] = mnz;
            sh_bb[3] = mxx; sh_bb[4] = mxy; sh_bb[5] = mxz;
        }
    }
    // zero hist
    for (int i = tid; i < NBINS; i += 1024) sh_hist[i] = 0;
    __syncthreads();

    const float bx0 = sh_bb[0], by0 = sh_bb[1], bz0 = sh_bb[2];
    const float ivx = 16.0f / fmaxf(sh_bb[3] - bx0, 1e-20f);
    const float ivy = 16.0f / fmaxf(sh_bb[4] - by0, 1e-20f);
    const float ivz = 16.0f / fmaxf(sh_bb[5] - bz0, 1e-20f);

    // ---- codes + histogram ----
    for (int j = 0; j < 16; j++) {
        const int i = tid + (j << 10);
        float px = p[3 * i + 0], py = p[3 * i + 1], pz = p[3 * i + 2];
        int cx = min(15, max(0, (int)((px - bx0) * ivx)));
        int cy = min(15, max(0, (int)((py - by0) * ivy)));
        int cz = min(15, max(0, (int)((pz - bz0) * ivz)));
        int code = (int)(mort4((unsigned)cx) | (mort4((unsigned)cy) << 1)
                         | (mort4((unsigned)cz) << 2));
        g_code[i] = code;
        atomicAdd(&sh_hist[code], 1);
    }
    __syncthreads();

    // ---- exclusive scan of 4096 bins (4 per thread) ----
    int b0 = sh_hist[4 * tid + 0];
    int b1 = sh_hist[4 * tid + 1];
    int b2 = sh_hist[4 * tid + 2];
    int b3 = sh_hist[4 * tid + 3];
    int tsum = b0 + b1 + b2 + b3;
    int v = tsum;
#pragma unroll
    for (int off = 1; off < 32; off <<= 1) {
        int n = __shfl_up_sync(0xffffffffu, v, off);
        if (lane >= off) v += n;
    }
    const int excl = v - tsum;
    if (lane == 31) sh_wt[wid] = v;
    __syncthreads();
    if (wid == 0) {
        int wv = sh_wt[lane];
        int sv = wv;
#pragma unroll
        for (int off = 1; off < 32; off <<= 1) {
            int n = __shfl_up_sync(0xffffffffu, sv, off);
            if (lane >= off) sv += n;
        }
        sh_wt[lane] = sv - wv;  // exclusive warp offsets
    }
    __syncthreads();
    const int toff = sh_wt[wid] + excl;
    sh_hist[4 * tid + 0] = toff;
    sh_hist[4 * tid + 1] = toff + b0;
    sh_hist[4 * tid + 2] = toff + b0 + b1;
    sh_hist[4 * tid + 3] = toff + b0 + b1 + b2;
    __syncthreads();

    // ---- scatter sorted coords + original indices ----
    for (int j = 0; j < 16; j++) {
        const int i = tid + (j << 10);
        const int code = g_code[i];
        const int pos = atomicAdd(&sh_hist[code], 1);
        g_sx[pos] = p[3 * i + 0];
        g_sy[pos] = p[3 * i + 1];
        g_sz[pos] = p[3 * i + 2];
        g_sidx[pos] = i;
    }
}

// ---------------------------------------------------------------------------
// 1) FPS, 512 threads x 32 Morton-sorted points per thread, exact chunk-bbox
//    pruning. Per iteration:
//      - chunk-bbox lower bound gates the 32-point scan (exact skip, same
//        epsilon argument as before -> d[] evolution bit-identical).
//      - level-1 reduce runs ONLY if some lane scanned (__any_sync); it uses
//        REDUX: fp32 distances are >=0 so float bits compare as ints ->
//        __reduce_max_sync(value bits) then __reduce_min_sync(selected key).
//        Key = (orig<<14)|sorted -> min key == min ORIGINAL index =>
//        jnp.argmax first-occurrence tie semantics preserved.
//      - two-barrier spine (round-8 style): lane0 STS red[wid]; bar; warp 0
//        REDUX over 16 warp results, writes cur + np_out; bar.
//    Scan math is the exact non-FMA chain matching the reference rounding.
// ---------------------------------------------------------------------------
__global__ __launch_bounds__(FPS_T, 1)
void fps_kernel(const float* __restrict__ p, float* __restrict__ np_out)
{
    extern __shared__ float sm[];
    float* sxT = sm;                 // [32][512]: sorted i -> [(i&31)][i>>5]
    float* syT = sm + NPTS;
    float* szT = sm + 2 * NPTS;
    __shared__ int   red_vi[NWARP];
    __shared__ int   red_os[NWARP];
    __shared__ float cur[3];

    const int tid  = threadIdx.x;
    const int lane = tid & 31;
    const int wid  = tid >> 5;

    // load sorted coords, transposed: sorted index i -> [(i&31)][i>>5]
    for (int j = 0; j < PPT; j++) {
        const int i = tid + (j << 9);
        const int col = ((i & 31) << 9) | (i >> 5);
        sxT[col] = g_sx[i];
        syT[col] = g_sy[i];
        szT[col] = g_sz[i];
    }

    // original ids of owned chunk (sorted [32*tid, 32*tid+31]), 2 per register
    unsigned oidp[PPT / 2];
#pragma unroll
    for (int j = 0; j < PPT / 2; j++) {
        unsigned a = (unsigned)g_sidx[(tid << 5) | (2 * j)];
        unsigned b = (unsigned)g_sidx[(tid << 5) | (2 * j + 1)];
        oidp[j] = a | (b << 16);
    }

    if (tid == 0) {
        cur[0] = p[0]; cur[1] = p[1]; cur[2] = p[2];
        np_out[0] = p[0]; np_out[1] = p[1]; np_out[2] = p[2];
    }
    __syncthreads();

    // chunk bbox (registers)
    float bxl = F_INF, byl = F_INF, bzl = F_INF;
    float bxh = -F_INF, byh = -F_INF, bzh = -F_INF;
#pragma unroll
    for (int k = 0; k < PPT; k++) {
        const int col = (k << 9) | tid;
        float x = sxT[col], y = syT[col], z = szT[col];
        bxl = fminf(bxl, x); bxh = fmaxf(bxh, x);
        byl = fminf(byl, y); byh = fmaxf(byh, y);
        bzl = fminf(bzl, z); bzh = fmaxf(bzh, z);
    }

    float d[PPT];
#pragma unroll
    for (int k = 0; k < PPT; k++) d[k] = F_INF;
    float my_v  = F_INF;              // forces scan at it=1
    int   my_os = 0x7fffffff;
    int   wvi = 0x7f800000;           // per-warp cached reduce result (value bits)
    int   wos = 0x7fffffff;

    for (int it = 1; it < MPTS; it++) {
        const float lx = cur[0], ly = cur[1], lz = cur[2];

        // chunk lower-bound dist^2
        float ex = fmaxf(fmaxf(bxl - lx, lx - bxh), 0.0f);
        float ey = fmaxf(fmaxf(byl - ly, ly - byh), 0.0f);
        float ez = fmaxf(fmaxf(bzl - lz, lz - bzh), 0.0f);
        float lb = ex * ex + ey * ey + ez * ez;

        const bool scanned = lb < my_v * 1.00002f;  // safety >> lb rounding err
        if (scanned) {
            float bv = -1.0f;
            int   bos = 0x7fffffff;
#pragma unroll
            for (int k = 0; k < PPT; k++) {
                const int col = (k << 9) | tid;
                float dx = __fsub_rn(sxT[col], lx);
                float dy = __fsub_rn(syT[col], ly);
                float dz = __fsub_rn(szT[col], lz);
                float s  = __fadd_rn(__fadd_rn(__fmul_rn(dx, dx), __fmul_rn(dy, dy)),
                                     __fmul_rn(dz, dz));
                float dn = fminf(d[k], s);
                d[k] = dn;
                const unsigned orig = (k & 1) ? (oidp[k >> 1] >> 16)
                                              : (oidp[k >> 1] & 0xffffu);
                const int os = (int)(orig << 14) | ((tid << 5) | k);
                if (dn > bv || (dn == bv && os < bos)) { bv = dn; bos = os; }
            }
            my_v = bv; my_os = bos;
        }
        if (__any_sync(0xffffffffu, scanned)) {
            // REDUX level-1: max by value bits (>=0 floats), min key on ties
            const int vi = __float_as_int(my_v);
            const int vmax = __reduce_max_sync(0xffffffffu, vi);
            const int ks = (vi == vmax) ? my_os : 0x7fffffff;
            const int kmin = __reduce_min_sync(0xffffffffu, ks);
            wvi = vmax; wos = kmin;
        }
        if (lane == 0) { red_vi[wid] = wvi; red_os[wid] = wos; }
        __syncthreads();

        if (wid == 0) {
            const int vi = (lane < NWARP) ? red_vi[lane] : (int)0x80000000;
            const int os = (lane < NWARP) ? red_os[lane] : 0x7fffffff;
            const int vmax = __reduce_max_sync(0xffffffffu, vi);
            const int ks = (vi == vmax) ? os : 0x7fffffff;
            const int kmin = __reduce_min_sync(0xffffffffu, ks);
            if (lane == 0) {
                const int rs = kmin & 0x3FFF;
                const int col = ((rs & 31) << 9) | (rs >> 5);
                float wx = sxT[col], wy = syT[col], wz = szT[col];
                cur[0] = wx; cur[1] = wy; cur[2] = wz;
                np_out[3 * it + 0] = wx;
                np_out[3 * it + 1] = wy;
                np_out[3 * it + 2] = wz;
            }
        }
        __syncthreads();
    }
}

// ---------------------------------------------------------------------------
// 2) kNN phase A: one thread per (query, chunk). Chunk coords staged in smem;
//    register-resident sorted top-16 with bubble insert.
// ---------------------------------------------------------------------------
__global__ __launch_bounds__(256)
void knn_kernel(const float* __restrict__ p, const float* __restrict__ np)
{
    __shared__ float sx[CHSZ], sy[CHSZ], sz[CHSZ];
    const int c = blockIdx.y;
    const int q = blockIdx.x * blockDim.x + threadIdx.x;

    for (int i = threadIdx.x; i < CHSZ; i += blockDim.x) {
        const int g = c * CHSZ + i;
        sx[i] = p[3 * g + 0];
        sy[i] = p[3 * g + 1];
        sz[i] = p[3 * g + 2];
    }
    __syncthreads();

    const float qx = np[3 * q + 0];
    const float qy = np[3 * q + 1];
    const float qz = np[3 * q + 2];

    float dk[KNN];
    int   ik[KNN];
#pragma unroll
    for (int t = 0; t < KNN; t++) { dk[t] = F_INF; ik[t] = 0; }

    for (int j = 0; j < CHSZ; j++) {
        float dx = qx - sx[j];
        float dy = qy - sy[j];
        float dz = qz - sz[j];
        float d2 = dx * dx + dy * dy + dz * dz;
        if (d2 < dk[KNN - 1]) {
            float cd = d2;
            int   ci = c * CHSZ + j;
#pragma unroll
            for (int t = 0; t < KNN; t++) {
                if (cd < dk[t]) {
                    float td = dk[t]; int ti = ik[t];
                    dk[t] = cd; ik[t] = ci;
                    cd = td; ci = ti;
                }
            }
        }
    }
    const int base = (q * NCHUNK + c) * KNN;
#pragma unroll
    for (int t = 0; t < KNN; t++) {
        g_cand_d[base + t] = dk[t];
        g_cand_i[base + t] = ik[t];
    }
}

// ---------------------------------------------------------------------------
// 3) Merge 8 sorted candidate lists -> top-16 set, gather, normalize,
//    max-pool to 67 dims. One warp per query.
// ---------------------------------------------------------------------------
__global__ __launch_bounds__(128)
void feat_kernel(const float* __restrict__ p, const float* __restrict__ x,
                 const float* __restrict__ np)
{
    const int w    = threadIdx.x >> 5;
    const int lane = threadIdx.x & 31;
    const int q    = blockIdx.x * 4 + w;

    __shared__ int s_nn[4][KNN];

    if (lane == 0) {
        int hpos[NCHUNK];
#pragma unroll
        for (int c = 0; c < NCHUNK; c++) hpos[c] = 0;
        for (int t = 0; t < KNN; t++) {
            float best = F_INF;
            int   bc   = 0;
#pragma unroll
            for (int c = 0; c < NCHUNK; c++) {
                float v = g_cand_d[(q * NCHUNK + c) * KNN + hpos[c]];
                if (v < best) { best = v; bc = c; }
            }
            s_nn[w][t] = g_cand_i[(q * NCHUNK + bc) * KNN + hpos[bc]];
            hpos[bc]++;
        }
    }
    __syncwarp();

    const float qx = np[3 * q + 0];
    const float qy = np[3 * q + 1];
    const float qz = np[3 * q + 2];

    float nr = -1.0f;
    if (lane < KNN) {
        int j = s_nn[w][lane];
        float rx = p[3 * j + 0] - qx;
        float ry = p[3 * j + 1] - qy;
        float rz = p[3 * j + 2] - qz;
        nr = sqrtf(rx * rx + ry * ry + rz * rz);
    }
#pragma unroll
    for (int off = 16; off > 0; off >>= 1)
        nr = fmaxf(nr, __shfl_xor_sync(0xffffffffu, nr, off));
    const float den = nr + 1e-8f;

    if (lane < 3) {
        const float qc = (lane == 0) ? qx : (lane == 1) ? qy : qz;
        float mv = -F_INF;
#pragma unroll
        for (int k = 0; k < KNN; k++) {
            int j = s_nn[w][k];
            mv = fmaxf(mv, p[3 * j + lane] - qc);
        }
        g_feat[q * DF + lane] = mv / den;
    }

    for (int xd = lane; xd < DIN; xd += 32) {
        float mv = -F_INF;
#pragma unroll
        for (int k = 0; k < KNN; k++) {
            int j = s_nn[w][k];
            mv = fmaxf(mv, x[j * DIN + xd]);
        }
        g_feat[q * DF + 3 + xd] = mv;
    }
}

// ---------------------------------------------------------------------------
// 4) h = feat @ W + b   (tiny GEMM: 4096x67x128)
// ---------------------------------------------------------------------------
__global__ __launch_bounds__(1024)
void mlp_kernel(const float* __restrict__ W, const float* __restrict__ b)
{
    __shared__ float sW[DF * DOUT];
    __shared__ float sF[8][DF];
    const int tid = threadIdx.x;
    for (int i = tid; i < DF * DOUT; i += 1024) sW[i] = W[i];
    const int qb = blockIdx.x * 8;
    for (int i = tid; i < 8 * DF; i += 1024) {
        int qq = i / DF, f = i - qq * DF;
        sF[qq][f] = g_feat[(qb + qq) * DF + f];
    }
    __syncthreads();
    const int od = tid & 127;
    const int qi = tid >> 7;
    float acc = b[od];
#pragma unroll
    for (int f = 0; f < DF; f++) acc += sF[qi][f] * sW[f * DOUT + od];
    g_h[(qb + qi) * DOUT + od] = acc;
}

// ---------------------------------------------------------------------------
// 5) BatchNorm training stats per output column (double accumulation)
// ---------------------------------------------------------------------------
__global__ __launch_bounds__(256)
void bn_stats_kernel(const float* __restrict__ gamma, const float* __restrict__ beta)
{
    const int col = blockIdx.x;
    const int tid = threadIdx.x;
    double s = 0.0, s2 = 0.0;
    for (int q = tid; q < MPTS; q += 256) {
        float v = g_h[q * DOUT + col];
        s  += (double)v;
        s2 += (double)v * (double)v;
    }
    __shared__ double sh_s[256], sh_s2[256];
    sh_s[tid] = s; sh_s2[tid] = s2;
    __syncthreads();
    for (int off = 128; off > 0; off >>= 1) {
        if (tid < off) { sh_s[tid] += sh_s[tid + off]; sh_s2[tid] += sh_s2[tid + off]; }
        __syncthreads();
    }
    if (tid == 0) {
        double mean = sh_s[0] / (double)MPTS;
        double var  = sh_s2[0] / (double)MPTS - mean * mean;
        float inv   = (float)(1.0 / sqrt(var + 1e-5));
        float sc    = gamma[col] * inv;
        g_scale[col] = sc;
        g_shift[col] = beta[col] - (float)mean * sc;
    }
}

// ---------------------------------------------------------------------------
// 6) normalize + ReLU -> output; write n_o tail
// ---------------------------------------------------------------------------
__global__ __launch_bounds__(1024)
void finalize_kernel(float* __restrict__ out, int tail)
{
    const int idx = blockIdx.x * 1024 + threadIdx.x;
    if (idx < MPTS * DOUT) {
        const int od = idx & 127;
        float v = g_h[idx] * g_scale[od] + g_shift[od];
        out[3 * MPTS + idx] = v > 0.0f ? v : 0.0f;
    }
    if (idx == 0) {
        for (int t = 0; t < tail; t++)
            out[3 * MPTS + MPTS * DOUT + t] = (float)MPTS;
    }
}

// ---------------------------------------------------------------------------
extern "C" void kernel_launch(void* const* d_in, const int* in_sizes, int n_in,
                              void* d_out, int out_size)
{
    const float* p     = (const float*)d_in[0];
    const float* x     = (const float*)d_in[1];
    // d_in[2] = offsets o (unused, single cloud)
    const float* W     = (const float*)d_in[3];
    const float* b     = (const float*)d_in[4];
    const float* gamma = (const float*)d_in[5];
    const float* beta  = (const float*)d_in[6];
    float* out = (float*)d_out;

    cudaFuncSetAttribute(fps_kernel, cudaFuncAttributeMaxDynamicSharedMemorySize,
                         3 * NPTS * (int)sizeof(float));

    prep_kernel<<<1, 1024>>>(p);

    fps_kernel<<<1, FPS_T, 3 * NPTS * sizeof(float)>>>(p, out);

    dim3 gA(MPTS / 256, NCHUNK);
    knn_kernel<<<gA, 256>>>(p, out);

    feat_kernel<<<MPTS / 4, 128>>>(p, x, out);

    mlp_kernel<<<MPTS / 8, 1024>>>(W, b);

    bn_stats_kernel<<<DOUT, 256>>>(gamma, beta);

    int tail = out_size - (3 * MPTS + MPTS * DOUT);
    if (tail < 0) tail = 0;
    finalize_kernel<<<(MPTS * DOUT + 1023) / 1024, 1024>>>(out, tail);
}